// round 5
// baseline (speedup 1.0000x reference)
#include <cuda_runtime.h>

#define NN 50000
#define NE 800000
#define IN_CH 64

// ---------------------------------------------------------------------------
// Scratch layout (single __device__ array; [0, ZERO_CNT) floats memset to 0
// at the start of every launch). All offsets are multiples of 4 floats (16B).
// ---------------------------------------------------------------------------
constexpr size_t OFF_DEG    = 0;                               // [NN]
constexpr size_t OFF_AGGX   = OFF_DEG   + NN;                  // [NN*64]
constexpr size_t OFF_A2     = OFF_AGGX  + (size_t)NN * 64;     // [NN*128]
constexpr size_t OFF_A3     = OFF_A2    + (size_t)NN * 128;    // [NN*32]
constexpr size_t OFF_FLAG   = OFF_A3    + (size_t)NN * 32;     // [4] (int flag)
constexpr size_t ZERO_CNT   = OFF_FLAG  + 4;                   // zeroed region end
constexpr size_t OFF_DINV   = ZERO_CNT;                        // [NN]
constexpr size_t OFF_H1     = OFF_DINV  + NN;                  // [NN*256]
constexpr size_t OFF_P2     = OFF_H1    + (size_t)NN * 256;    // [NN*128]
constexpr size_t OFF_H2     = OFF_P2    + (size_t)NN * 128;    // [NN*128]
constexpr size_t OFF_P3     = OFF_H2    + (size_t)NN * 128;    // [NN*32]
constexpr size_t OFF_WREL3  = OFF_P3    + (size_t)NN * 32;     // [128*32]
constexpr size_t OFF_WROOT3 = OFF_WREL3 + 128 * 32;            // [128*32]
constexpr size_t OFF_B3     = OFF_WROOT3 + 128 * 32;           // [32]
constexpr size_t OFF_EIDX   = OFF_B3    + 32;                  // [2*NE] ints (src|dst)
constexpr size_t TOTAL_F    = OFF_EIDX  + (size_t)2 * NE;

__device__ __align__(128) float g_scratch[TOTAL_F];

// ---------------------------------------------------------------------------
// Edge-index dtype detection + conversion.
// int64 little-endian with values < 50000 => every odd 32-bit word is 0.
// int32 => odd words are src indices (random in [0, 50000)), ~surely nonzero.
// flag = 1 -> int32 data, flag = 0 -> int64 data.
// Converted indices are clamped to [0, NN) so a wrong guess can never produce
// an illegal access (valid data is unaffected: indices already in range).
// ---------------------------------------------------------------------------
__global__ void detect_kernel(const unsigned int* __restrict__ raw, int* __restrict__ flag) {
    int t = threadIdx.x;
    unsigned int v = 0;
    for (int i = t; i < 512; i += blockDim.x) v |= raw[2 * i + 1];
    if (__syncthreads_or(v != 0) && t == 0) *flag = 1;
}

__global__ void convert_kernel(const void* __restrict__ raw, const int* __restrict__ flag,
                               int* __restrict__ eidx) {
    int i = blockIdx.x * blockDim.x + threadIdx.x;
    if (i < 2 * NE) {
        int v = (*flag) ? ((const int*)raw)[i]
                        : (int)((const long long*)raw)[i];
        eidx[i] = min(max(v, 0), NN - 1);
    }
}

// ---------------------------------------------------------------------------
// Degree kernels
// ---------------------------------------------------------------------------
__global__ void deg_kernel(const int* __restrict__ dst, float* __restrict__ deg) {
    int e = blockIdx.x * blockDim.x + threadIdx.x;
    if (e < NE) atomicAdd(&deg[dst[e]], 1.0f);
}

__global__ void dinv_kernel(const float* __restrict__ deg, float* __restrict__ dinv) {
    int i = blockIdx.x * blockDim.x + threadIdx.x;
    if (i < NN) {
        float d = deg[i];
        dinv[i] = d > 0.0f ? 1.0f / d : 0.0f;
    }
}

// ---------------------------------------------------------------------------
// Pack the 4 head weight matrices into concatenated [128,32] buffers
// ---------------------------------------------------------------------------
__global__ void pack3_kernel(const float* __restrict__ Wmu_rel, const float* __restrict__ Wls_rel,
                             const float* __restrict__ Wmu_root, const float* __restrict__ Wls_root,
                             const float* __restrict__ bmu, const float* __restrict__ bls,
                             float* __restrict__ Wrel3, float* __restrict__ Wroot3,
                             float* __restrict__ b3) {
    int i = blockIdx.x * blockDim.x + threadIdx.x;
    if (i < 128 * 32) {
        int k = i / 32, n = i % 32;
        Wrel3[i]  = (n < 16) ? Wmu_rel[k * 16 + n]  : Wls_rel[k * 16 + (n - 16)];
        Wroot3[i] = (n < 16) ? Wmu_root[k * 16 + n] : Wls_root[k * 16 + (n - 16)];
        if (i < 32) b3[i] = (i < 16) ? bmu[i] : bls[i - 16];
    }
}

// ---------------------------------------------------------------------------
// Edge scatter: agg[dst,:] += P[src,:], float4 gather + red.global.add.v4
// Consecutive threads cover one edge's row -> coalesced gather+scatter.
// ---------------------------------------------------------------------------
template <int D>
__global__ void scatter_kernel(const int* __restrict__ srcArr, const int* __restrict__ dstArr,
                               const float* __restrict__ P, float* __restrict__ agg) {
    constexpr int C = D / 4;
    int idx = blockIdx.x * blockDim.x + threadIdx.x;
    if (idx >= NE * C) return;
    int e = idx / C;
    int c = idx % C;
    int src = srcArr[e];
    int dst = dstArr[e];
    const float4 v = *(const float4*)(P + (size_t)src * D + c * 4);
    float* p = agg + (size_t)dst * D + c * 4;
    asm volatile("red.global.add.v4.f32 [%0], {%1, %2, %3, %4};"
                 :: "l"(p), "f"(v.x), "f"(v.y), "f"(v.z), "f"(v.w)
                 : "memory");
}

// ---------------------------------------------------------------------------
// GEMM family: 64xBN tiles, BK=16, 4x4 register tile per thread.
// ---------------------------------------------------------------------------
template <int BN>
__global__ __launch_bounds__(16 * (BN / 4))
void gemm_proj(const float* __restrict__ A, const float* __restrict__ W,
               float* __restrict__ C, int M, int K, int N) {
    constexpr int BM = 64, BK = 16, TM = 4, TN = 4;
    constexpr int TX = BN / TN;
    constexpr int NT = (BM / TM) * TX;
    __shared__ float As[BK][BM];
    __shared__ float Bs[BK][BN];
    int t  = threadIdx.x;
    int m0 = blockIdx.x * BM;
    int n0 = blockIdx.y * BN;
    int tr = t / TX, tc = t % TX;
    float acc[TM][TN] = {};
    for (int k0 = 0; k0 < K; k0 += BK) {
        for (int i = t; i < BM * BK / 4; i += NT) {
            int row = i / (BK / 4);
            int c4  = i % (BK / 4);
            float4 v = make_float4(0.f, 0.f, 0.f, 0.f);
            int m = m0 + row;
            if (m < M) v = *(const float4*)(A + (size_t)m * K + k0 + c4 * 4);
            As[c4 * 4 + 0][row] = v.x;
            As[c4 * 4 + 1][row] = v.y;
            As[c4 * 4 + 2][row] = v.z;
            As[c4 * 4 + 3][row] = v.w;
        }
        for (int i = t; i < BK * BN / 4; i += NT) {
            int row = i / (BN / 4);
            int c4  = i % (BN / 4);
            *(float4*)(&Bs[row][c4 * 4]) =
                *(const float4*)(W + (size_t)(k0 + row) * N + n0 + c4 * 4);
        }
        __syncthreads();
#pragma unroll
        for (int kk = 0; kk < BK; kk++) {
            float a[TM], b[TN];
#pragma unroll
            for (int i = 0; i < TM; i++) a[i] = As[kk][tr * TM + i];
#pragma unroll
            for (int j = 0; j < TN; j++) b[j] = Bs[kk][tc * TN + j];
#pragma unroll
            for (int i = 0; i < TM; i++)
#pragma unroll
                for (int j = 0; j < TN; j++) acc[i][j] += a[i] * b[j];
        }
        __syncthreads();
    }
#pragma unroll
    for (int i = 0; i < TM; i++) {
        int m = m0 + tr * TM + i;
        if (m < M) {
            float4 v = make_float4(acc[i][0], acc[i][1], acc[i][2], acc[i][3]);
            *(float4*)(C + (size_t)m * N + n0 + tc * TN) = v;
        }
    }
}

// Layer 1: OUT = relu( (Agg * dinv[m]) @ Wa + X @ Wb + bias ),  KA=KB=64, N=256
__global__ __launch_bounds__(256)
void layer1_kernel(const float* __restrict__ Agg, const float* __restrict__ dinv,
                   const float* __restrict__ Wa,
                   const float* __restrict__ X, const float* __restrict__ Wb,
                   const float* __restrict__ bias, float* __restrict__ OUT,
                   int M) {
    constexpr int BM = 64, BN = 64, BK = 16, TM = 4, TN = 4;
    constexpr int TX = BN / TN;
    constexpr int NT = 256;
    constexpr int K = 64, N = 256;
    __shared__ float As[BK][BM];
    __shared__ float Bs[BK][BN];
    int t  = threadIdx.x;
    int m0 = blockIdx.x * BM;
    int n0 = blockIdx.y * BN;
    int tr = t / TX, tc = t % TX;
    float acc[TM][TN] = {};
#pragma unroll
    for (int phase = 0; phase < 2; phase++) {
        const float* A = phase == 0 ? Agg : X;
        const float* W = phase == 0 ? Wa : Wb;
        for (int k0 = 0; k0 < K; k0 += BK) {
            for (int i = t; i < BM * BK / 4; i += NT) {
                int row = i / (BK / 4);
                int c4  = i % (BK / 4);
                float4 v = make_float4(0.f, 0.f, 0.f, 0.f);
                int m = m0 + row;
                if (m < M) {
                    v = *(const float4*)(A + (size_t)m * K + k0 + c4 * 4);
                    if (phase == 0) {
                        float s = dinv[m];
                        v.x *= s; v.y *= s; v.z *= s; v.w *= s;
                    }
                }
                As[c4 * 4 + 0][row] = v.x;
                As[c4 * 4 + 1][row] = v.y;
                As[c4 * 4 + 2][row] = v.z;
                As[c4 * 4 + 3][row] = v.w;
            }
            for (int i = t; i < BK * BN / 4; i += NT) {
                int row = i / (BN / 4);
                int c4  = i % (BN / 4);
                *(float4*)(&Bs[row][c4 * 4]) =
                    *(const float4*)(W + (size_t)(k0 + row) * N + n0 + c4 * 4);
            }
            __syncthreads();
#pragma unroll
            for (int kk = 0; kk < BK; kk++) {
                float a[TM], b[TN];
#pragma unroll
                for (int i = 0; i < TM; i++) a[i] = As[kk][tr * TM + i];
#pragma unroll
                for (int j = 0; j < TN; j++) b[j] = Bs[kk][tc * TN + j];
#pragma unroll
                for (int i = 0; i < TM; i++)
#pragma unroll
                    for (int j = 0; j < TN; j++) acc[i][j] += a[i] * b[j];
            }
            __syncthreads();
        }
    }
    float bv[TN];
#pragma unroll
    for (int j = 0; j < TN; j++) bv[j] = bias[n0 + tc * TN + j];
#pragma unroll
    for (int i = 0; i < TM; i++) {
        int m = m0 + tr * TM + i;
        if (m < M) {
            float4 v;
            v.x = fmaxf(acc[i][0] + bv[0], 0.f);
            v.y = fmaxf(acc[i][1] + bv[1], 0.f);
            v.z = fmaxf(acc[i][2] + bv[2], 0.f);
            v.w = fmaxf(acc[i][3] + bv[3], 0.f);
            *(float4*)(OUT + (size_t)m * N + n0 + tc * TN) = v;
        }
    }
}

// Epilogue GEMM: OUT = act( ADD[m,n]*dinv[m] + bias[n] + X @ Wroot )
// SPLIT: cols [0,16) -> OUT, cols [16,32) -> OUT + NN*16 (mu / logstd halves)
template <int BN, bool RELU, bool SPLIT>
__global__ __launch_bounds__(16 * (BN / 4))
void out_kernel(const float* __restrict__ X, const float* __restrict__ Wroot,
                const float* __restrict__ ADD, const float* __restrict__ dinv,
                const float* __restrict__ bias, float* __restrict__ OUT,
                int M, int K, int N) {
    constexpr int BM = 64, BK = 16, TM = 4, TN = 4;
    constexpr int TX = BN / TN;
    constexpr int NT = (BM / TM) * TX;
    __shared__ float As[BK][BM];
    __shared__ float Bs[BK][BN];
    int t  = threadIdx.x;
    int m0 = blockIdx.x * BM;
    int n0 = blockIdx.y * BN;
    int tr = t / TX, tc = t % TX;
    float acc[TM][TN] = {};
    for (int k0 = 0; k0 < K; k0 += BK) {
        for (int i = t; i < BM * BK / 4; i += NT) {
            int row = i / (BK / 4);
            int c4  = i % (BK / 4);
            float4 v = make_float4(0.f, 0.f, 0.f, 0.f);
            int m = m0 + row;
            if (m < M) v = *(const float4*)(X + (size_t)m * K + k0 + c4 * 4);
            As[c4 * 4 + 0][row] = v.x;
            As[c4 * 4 + 1][row] = v.y;
            As[c4 * 4 + 2][row] = v.z;
            As[c4 * 4 + 3][row] = v.w;
        }
        for (int i = t; i < BK * BN / 4; i += NT) {
            int row = i / (BN / 4);
            int c4  = i % (BN / 4);
            *(float4*)(&Bs[row][c4 * 4]) =
                *(const float4*)(Wroot + (size_t)(k0 + row) * N + n0 + c4 * 4);
        }
        __syncthreads();
#pragma unroll
        for (int kk = 0; kk < BK; kk++) {
            float a[TM], b[TN];
#pragma unroll
            for (int i = 0; i < TM; i++) a[i] = As[kk][tr * TM + i];
#pragma unroll
            for (int j = 0; j < TN; j++) b[j] = Bs[kk][tc * TN + j];
#pragma unroll
            for (int i = 0; i < TM; i++)
#pragma unroll
                for (int j = 0; j < TN; j++) acc[i][j] += a[i] * b[j];
        }
        __syncthreads();
    }
    float bv[TN];
#pragma unroll
    for (int j = 0; j < TN; j++) bv[j] = bias[n0 + tc * TN + j];
#pragma unroll
    for (int i = 0; i < TM; i++) {
        int m = m0 + tr * TM + i;
        if (m < M) {
            float s = dinv[m];
            const float4 av = *(const float4*)(ADD + (size_t)m * N + n0 + tc * TN);
            float4 v;
            v.x = acc[i][0] + bv[0] + av.x * s;
            v.y = acc[i][1] + bv[1] + av.y * s;
            v.z = acc[i][2] + bv[2] + av.z * s;
            v.w = acc[i][3] + bv[3] + av.w * s;
            if (RELU) {
                v.x = fmaxf(v.x, 0.f); v.y = fmaxf(v.y, 0.f);
                v.z = fmaxf(v.z, 0.f); v.w = fmaxf(v.w, 0.f);
            }
            if (SPLIT) {
                int n = n0 + tc * TN;  // all 4 cols land in the same half (tc*4)
                float* dst = (n < 16) ? (OUT + (size_t)m * 16 + n)
                                      : (OUT + (size_t)NN * 16 + (size_t)m * 16 + (n - 16));
                *(float4*)dst = v;
            } else {
                *(float4*)(OUT + (size_t)m * N + n0 + tc * TN) = v;
            }
        }
    }
}

// ---------------------------------------------------------------------------
// Launch
// ---------------------------------------------------------------------------
extern "C" void kernel_launch(void* const* d_in, const int* in_sizes, int n_in,
                              void* d_out, int out_size) {
    // Input binding: detect metadata ordering scheme from in_sizes[0].
    const float *x, *W1_rel, *b1, *W1_root, *W2_rel, *b2, *W2_root;
    const float *Wmu_rel, *bmu, *Wmu_root, *Wls_rel, *bls, *Wls_root;
    const void* ei_raw;

    if (in_sizes[0] == NN * IN_CH) {
        // dict order
        x        = (const float*)d_in[0];
        W1_rel   = (const float*)d_in[1];
        b1       = (const float*)d_in[2];
        W1_root  = (const float*)d_in[3];
        W2_rel   = (const float*)d_in[4];
        b2       = (const float*)d_in[5];
        W2_root  = (const float*)d_in[6];
        Wmu_rel  = (const float*)d_in[7];
        bmu      = (const float*)d_in[8];
        Wmu_root = (const float*)d_in[9];
        Wls_rel  = (const float*)d_in[10];
        bls      = (const float*)d_in[11];
        Wls_root = (const float*)d_in[12];
        ei_raw   = d_in[13];
    } else {
        // alphabetical order
        W1_rel   = (const float*)d_in[0];
        W1_root  = (const float*)d_in[1];
        W2_rel   = (const float*)d_in[2];
        W2_root  = (const float*)d_in[3];
        Wls_rel  = (const float*)d_in[4];
        Wls_root = (const float*)d_in[5];
        Wmu_rel  = (const float*)d_in[6];
        Wmu_root = (const float*)d_in[7];
        b1       = (const float*)d_in[8];
        b2       = (const float*)d_in[9];
        bls      = (const float*)d_in[10];
        bmu      = (const float*)d_in[11];
        ei_raw   = d_in[12];
        x        = (const float*)d_in[13];
    }
    float* out = (float*)d_out;

    float* base = nullptr;
    cudaGetSymbolAddress((void**)&base, g_scratch);
    float* deg    = base + OFF_DEG;
    float* aggx   = base + OFF_AGGX;
    float* a2     = base + OFF_A2;
    float* a3     = base + OFF_A3;
    int*   flag   = (int*)(base + OFF_FLAG);
    float* dinv   = base + OFF_DINV;
    float* h1     = base + OFF_H1;
    float* p2     = base + OFF_P2;
    float* h2     = base + OFF_H2;
    float* p3     = base + OFF_P3;
    float* Wrel3  = base + OFF_WREL3;
    float* Wroot3 = base + OFF_WROOT3;
    float* b3     = base + OFF_B3;
    int*   eidx   = (int*)(base + OFF_EIDX);
    int*   esrc   = eidx;
    int*   edst   = eidx + NE;

    // zero accumulators + flag
    cudaMemsetAsync(base, 0, ZERO_CNT * sizeof(float), 0);

    // edge-index dtype detection + conversion to clamped int32 src/dst arrays
    detect_kernel<<<1, 256>>>((const unsigned int*)ei_raw, flag);
    convert_kernel<<<(2 * NE + 255) / 256, 256>>>(ei_raw, flag, eidx);

    // prep
    pack3_kernel<<<(128 * 32 + 255) / 256, 256>>>(Wmu_rel, Wls_rel, Wmu_root, Wls_root,
                                                  bmu, bls, Wrel3, Wroot3, b3);
    deg_kernel<<<(NE + 255) / 256, 256>>>(edst, deg);
    dinv_kernel<<<(NN + 255) / 256, 256>>>(deg, dinv);

    const int MB = (NN + 63) / 64;  // 782

    // layer 1: aggregate x (64), then fused dual GEMM -> h1 [NN,256]
    scatter_kernel<64><<<(NE * 16 + 255) / 256, 256>>>(esrc, edst, x, aggx);
    layer1_kernel<<<dim3(MB, 4), 256>>>(aggx, dinv, W1_rel, x, W1_root, b1, h1, NN);

    // layer 2: project h1 -> p2 [NN,128], aggregate, epilogue GEMM -> h2
    gemm_proj<64><<<dim3(MB, 2), 256>>>(h1, W2_rel, p2, NN, 256, 128);
    scatter_kernel<128><<<(NE * 32 + 255) / 256, 256>>>(esrc, edst, p2, a2);
    out_kernel<64, true, false><<<dim3(MB, 2), 256>>>(h1, W2_root, a2, dinv, b2, h2,
                                                      NN, 256, 128);

    // heads: project h2 -> p3 [NN,32], aggregate, epilogue GEMM -> (mu|logstd)
    gemm_proj<32><<<dim3(MB, 1), 128>>>(h2, Wrel3, p3, NN, 128, 32);
    scatter_kernel<32><<<(NE * 8 + 255) / 256, 256>>>(esrc, edst, p3, a3);
    out_kernel<32, false, true><<<dim3(MB, 1), 128>>>(h2, Wroot3, a3, dinv, b3, out,
                                                      NN, 128, 32);
}

// round 6
// speedup vs baseline: 1.1698x; 1.1698x over previous
#include <cuda_runtime.h>
#include <mma.h>

using namespace nvcuda;

#define NN 50000
#define NE 800000
#define IN_CH 64

// ---------------------------------------------------------------------------
// Scratch layout (single __device__ array; [0, ZERO_CNT) floats memset to 0
// at the start of every launch). All offsets are multiples of 4 floats (16B).
// ---------------------------------------------------------------------------
constexpr size_t OFF_DEG    = 0;                               // [NN]
constexpr size_t OFF_AGGX   = OFF_DEG   + NN;                  // [NN*64]
constexpr size_t OFF_A2     = OFF_AGGX  + (size_t)NN * 64;     // [NN*128]
constexpr size_t OFF_A3     = OFF_A2    + (size_t)NN * 128;    // [NN*32]
constexpr size_t OFF_FLAG   = OFF_A3    + (size_t)NN * 32;     // [4] (int flag)
constexpr size_t ZERO_CNT   = OFF_FLAG  + 4;                   // zeroed region end
constexpr size_t OFF_DINV   = ZERO_CNT;                        // [NN]
constexpr size_t OFF_H1     = OFF_DINV  + NN;                  // [NN*256]
constexpr size_t OFF_P2     = OFF_H1    + (size_t)NN * 256;    // [NN*128]
constexpr size_t OFF_H2     = OFF_P2    + (size_t)NN * 128;    // [NN*128]
constexpr size_t OFF_P3     = OFF_H2    + (size_t)NN * 128;    // [NN*32]
constexpr size_t OFF_WREL3  = OFF_P3    + (size_t)NN * 32;     // [128*32]
constexpr size_t OFF_WROOT3 = OFF_WREL3 + 128 * 32;            // [128*32]
constexpr size_t OFF_B3     = OFF_WROOT3 + 128 * 32;           // [32]
constexpr size_t OFF_EIDX   = OFF_B3    + 32;                  // [2*NE] ints (src|dst)
constexpr size_t TOTAL_F    = OFF_EIDX  + (size_t)2 * NE;

__device__ __align__(128) float g_scratch[TOTAL_F];

// ---------------------------------------------------------------------------
// Edge-index dtype detection + conversion (clamped to [0, NN) for safety).
// ---------------------------------------------------------------------------
__global__ void detect_kernel(const unsigned int* __restrict__ raw, int* __restrict__ flag) {
    int t = threadIdx.x;
    unsigned int v = 0;
    for (int i = t; i < 512; i += blockDim.x) v |= raw[2 * i + 1];
    if (__syncthreads_or(v != 0) && t == 0) *flag = 1;
}

__global__ void convert_kernel(const void* __restrict__ raw, const int* __restrict__ flag,
                               int* __restrict__ eidx) {
    int i = blockIdx.x * blockDim.x + threadIdx.x;
    if (i < 2 * NE) {
        int v = (*flag) ? ((const int*)raw)[i]
                        : (int)((const long long*)raw)[i];
        eidx[i] = min(max(v, 0), NN - 1);
    }
}

// ---------------------------------------------------------------------------
// Degree kernels
// ---------------------------------------------------------------------------
__global__ void deg_kernel(const int* __restrict__ dst, float* __restrict__ deg) {
    int e = blockIdx.x * blockDim.x + threadIdx.x;
    if (e < NE) atomicAdd(&deg[dst[e]], 1.0f);
}

__global__ void dinv_kernel(const float* __restrict__ deg, float* __restrict__ dinv) {
    int i = blockIdx.x * blockDim.x + threadIdx.x;
    if (i < NN) {
        float d = deg[i];
        dinv[i] = d > 0.0f ? 1.0f / d : 0.0f;
    }
}

// ---------------------------------------------------------------------------
// Pack the 4 head weight matrices into concatenated [128,32] buffers
// ---------------------------------------------------------------------------
__global__ void pack3_kernel(const float* __restrict__ Wmu_rel, const float* __restrict__ Wls_rel,
                             const float* __restrict__ Wmu_root, const float* __restrict__ Wls_root,
                             const float* __restrict__ bmu, const float* __restrict__ bls,
                             float* __restrict__ Wrel3, float* __restrict__ Wroot3,
                             float* __restrict__ b3) {
    int i = blockIdx.x * blockDim.x + threadIdx.x;
    if (i < 128 * 32) {
        int k = i / 32, n = i % 32;
        Wrel3[i]  = (n < 16) ? Wmu_rel[k * 16 + n]  : Wls_rel[k * 16 + (n - 16)];
        Wroot3[i] = (n < 16) ? Wmu_root[k * 16 + n] : Wls_root[k * 16 + (n - 16)];
        if (i < 32) b3[i] = (i < 16) ? bmu[i] : bls[i - 16];
    }
}

// ---------------------------------------------------------------------------
// Edge scatter: agg[dst,:] += P[src,:], float4 gather + red.global.add.v4
// ---------------------------------------------------------------------------
template <int D>
__global__ void scatter_kernel(const int* __restrict__ srcArr, const int* __restrict__ dstArr,
                               const float* __restrict__ P, float* __restrict__ agg) {
    constexpr int C = D / 4;
    int idx = blockIdx.x * blockDim.x + threadIdx.x;
    if (idx >= NE * C) return;
    int e = idx / C;
    int c = idx % C;
    int src = srcArr[e];
    int dst = dstArr[e];
    const float4 v = *(const float4*)(P + (size_t)src * D + c * 4);
    float* p = agg + (size_t)dst * D + c * 4;
    asm volatile("red.global.add.v4.f32 [%0], {%1, %2, %3, %4};"
                 :: "l"(p), "f"(v.x), "f"(v.y), "f"(v.z), "f"(v.w)
                 : "memory");
}

// ---------------------------------------------------------------------------
// tf32 wmma GEMM: 128xBN block tile, BK=16 (2 k-steps of 8), 4 x (BN/32)
// warps, each warp 32x32 (2x2 m16n16k8 fragments), fp32 accumulate.
// tf32 conversion happens once at the smem store.
//
// DUAL     : c = (A*dinv[m])@W + A2@W2 (two phases, same K)
// HAS_ADD  : epilogue += ADD[m,n]*dinv[m]
// bias     : added if non-null
// RELU     : epilogue relu
// SPLIT    : N=32 -> cols [0,16) at OUT[m*16+n], cols [16,32) at OUT+NN*16
// ---------------------------------------------------------------------------
template <int BN, bool DUAL, bool HAS_ADD, bool RELU, bool SPLIT>
__global__ __launch_bounds__(32 * 4 * (BN / 32))
void mm_kernel(const float* __restrict__ A, const float* __restrict__ W,
               const float* __restrict__ A2, const float* __restrict__ W2,
               const float* __restrict__ ADD, const float* __restrict__ dinv,
               const float* __restrict__ bias, float* __restrict__ OUT,
               int M, int K, int N) {
    constexpr int BM = 128, BK = 16;
    constexpr int WN = BN / 32;          // warp-grid cols
    constexpr int NT = 128 * WN;         // threads
    constexpr int LDA = BK + 8;          // 24
    constexpr int LDB = BN + 8;
    constexpr int LDC = BN + 8;
    constexpr int SZ_AB = BM * LDA + BK * LDB;
    constexpr int SZ_C  = BM * LDC;
    constexpr int SMEM_FLOATS = SZ_AB > SZ_C ? SZ_AB : SZ_C;
    __shared__ __align__(16) float smem[SMEM_FLOATS];
    float* As = smem;
    float* Bs = smem + BM * LDA;
    float* Cs = smem;                    // aliased over As/Bs (sync-separated)

    int t    = threadIdx.x;
    int warp = t >> 5;
    int wm   = warp & 3;                 // warp row 0..3
    int wn   = warp >> 2;                // warp col 0..WN-1
    int m0   = blockIdx.x * BM;
    int n0   = blockIdx.y * BN;

    wmma::fragment<wmma::accumulator, 16, 16, 8, float> c[2][2];
#pragma unroll
    for (int i = 0; i < 2; i++)
#pragma unroll
        for (int j = 0; j < 2; j++) wmma::fill_fragment(c[i][j], 0.0f);

    const int nPhase = DUAL ? 2 : 1;
    for (int ph = 0; ph < nPhase; ph++) {
        const float* Ap = (DUAL && ph == 1) ? A2 : A;
        const float* Wp = (DUAL && ph == 1) ? W2 : W;
        for (int k0 = 0; k0 < K; k0 += BK) {
            // load A tile BMxBK (tf32-convert into smem)
            for (int i = t; i < BM * BK / 4; i += NT) {
                int row = i / (BK / 4);
                int c4  = i % (BK / 4);
                float4 v = make_float4(0.f, 0.f, 0.f, 0.f);
                int m = m0 + row;
                if (m < M) {
                    v = *(const float4*)(Ap + (size_t)m * K + k0 + c4 * 4);
                    if (DUAL && ph == 0) {
                        float s = dinv[m];
                        v.x *= s; v.y *= s; v.z *= s; v.w *= s;
                    }
                }
                float* d = As + row * LDA + c4 * 4;
                d[0] = wmma::__float_to_tf32(v.x);
                d[1] = wmma::__float_to_tf32(v.y);
                d[2] = wmma::__float_to_tf32(v.z);
                d[3] = wmma::__float_to_tf32(v.w);
            }
            // load B tile BKxBN (tf32-convert into smem)
            for (int i = t; i < BK * BN / 4; i += NT) {
                int row = i / (BN / 4);
                int c4  = i % (BN / 4);
                float4 v = *(const float4*)(Wp + (size_t)(k0 + row) * N + n0 + c4 * 4);
                float* d = Bs + row * LDB + c4 * 4;
                d[0] = wmma::__float_to_tf32(v.x);
                d[1] = wmma::__float_to_tf32(v.y);
                d[2] = wmma::__float_to_tf32(v.z);
                d[3] = wmma::__float_to_tf32(v.w);
            }
            __syncthreads();
#pragma unroll
            for (int kk = 0; kk < BK; kk += 8) {
                wmma::fragment<wmma::matrix_a, 16, 16, 8, wmma::precision::tf32, wmma::row_major> a[2];
                wmma::fragment<wmma::matrix_b, 16, 16, 8, wmma::precision::tf32, wmma::row_major> b[2];
#pragma unroll
                for (int i = 0; i < 2; i++)
                    wmma::load_matrix_sync(a[i], As + (wm * 32 + i * 16) * LDA + kk, LDA);
#pragma unroll
                for (int j = 0; j < 2; j++)
                    wmma::load_matrix_sync(b[j], Bs + kk * LDB + wn * 32 + j * 16, LDB);
#pragma unroll
                for (int i = 0; i < 2; i++)
#pragma unroll
                    for (int j = 0; j < 2; j++)
                        wmma::mma_sync(c[i][j], a[i], b[j], c[i][j]);
            }
            __syncthreads();
        }
    }

    // stage C in smem, then fused epilogue to global
#pragma unroll
    for (int i = 0; i < 2; i++)
#pragma unroll
        for (int j = 0; j < 2; j++)
            wmma::store_matrix_sync(Cs + (wm * 32 + i * 16) * LDC + wn * 32 + j * 16,
                                    c[i][j], LDC, wmma::mem_row_major);
    __syncthreads();

    for (int i = t; i < BM * BN / 4; i += NT) {
        int row = i / (BN / 4);
        int c4  = i % (BN / 4);
        int m = m0 + row;
        if (m >= M) continue;
        float4 v = *(float4*)(Cs + row * LDC + c4 * 4);
        int n = n0 + c4 * 4;
        if (bias) {
            v.x += bias[n + 0]; v.y += bias[n + 1];
            v.z += bias[n + 2]; v.w += bias[n + 3];
        }
        if (HAS_ADD) {
            float s = dinv[m];
            const float4 av = *(const float4*)(ADD + (size_t)m * N + n);
            v.x += av.x * s; v.y += av.y * s; v.z += av.z * s; v.w += av.w * s;
        }
        if (RELU) {
            v.x = fmaxf(v.x, 0.f); v.y = fmaxf(v.y, 0.f);
            v.z = fmaxf(v.z, 0.f); v.w = fmaxf(v.w, 0.f);
        }
        if (SPLIT) {
            float* dptr = (n < 16) ? (OUT + (size_t)m * 16 + n)
                                   : (OUT + (size_t)NN * 16 + (size_t)m * 16 + (n - 16));
            *(float4*)dptr = v;
        } else {
            *(float4*)(OUT + (size_t)m * N + n) = v;
        }
    }
}

// ---------------------------------------------------------------------------
// Launch
// ---------------------------------------------------------------------------
extern "C" void kernel_launch(void* const* d_in, const int* in_sizes, int n_in,
                              void* d_out, int out_size) {
    // Input binding: detect metadata ordering scheme from in_sizes[0].
    const float *x, *W1_rel, *b1, *W1_root, *W2_rel, *b2, *W2_root;
    const float *Wmu_rel, *bmu, *Wmu_root, *Wls_rel, *bls, *Wls_root;
    const void* ei_raw;

    if (in_sizes[0] == NN * IN_CH) {
        // dict order
        x        = (const float*)d_in[0];
        W1_rel   = (const float*)d_in[1];
        b1       = (const float*)d_in[2];
        W1_root  = (const float*)d_in[3];
        W2_rel   = (const float*)d_in[4];
        b2       = (const float*)d_in[5];
        W2_root  = (const float*)d_in[6];
        Wmu_rel  = (const float*)d_in[7];
        bmu      = (const float*)d_in[8];
        Wmu_root = (const float*)d_in[9];
        Wls_rel  = (const float*)d_in[10];
        bls      = (const float*)d_in[11];
        Wls_root = (const float*)d_in[12];
        ei_raw   = d_in[13];
    } else {
        // alphabetical order
        W1_rel   = (const float*)d_in[0];
        W1_root  = (const float*)d_in[1];
        W2_rel   = (const float*)d_in[2];
        W2_root  = (const float*)d_in[3];
        Wls_rel  = (const float*)d_in[4];
        Wls_root = (const float*)d_in[5];
        Wmu_rel  = (const float*)d_in[6];
        Wmu_root = (const float*)d_in[7];
        b1       = (const float*)d_in[8];
        b2       = (const float*)d_in[9];
        bls      = (const float*)d_in[10];
        bmu      = (const float*)d_in[11];
        ei_raw   = d_in[12];
        x        = (const float*)d_in[13];
    }
    float* out = (float*)d_out;

    float* base = nullptr;
    cudaGetSymbolAddress((void**)&base, g_scratch);
    float* deg    = base + OFF_DEG;
    float* aggx   = base + OFF_AGGX;
    float* a2     = base + OFF_A2;
    float* a3     = base + OFF_A3;
    int*   flag   = (int*)(base + OFF_FLAG);
    float* dinv   = base + OFF_DINV;
    float* h1     = base + OFF_H1;
    float* p2     = base + OFF_P2;
    float* h2     = base + OFF_H2;
    float* p3     = base + OFF_P3;
    float* Wrel3  = base + OFF_WREL3;
    float* Wroot3 = base + OFF_WROOT3;
    float* b3     = base + OFF_B3;
    int*   eidx   = (int*)(base + OFF_EIDX);
    int*   esrc   = eidx;
    int*   edst   = eidx + NE;

    // zero accumulators + flag
    cudaMemsetAsync(base, 0, ZERO_CNT * sizeof(float), 0);

    // edge-index dtype detection + conversion to clamped int32 src/dst arrays
    detect_kernel<<<1, 256>>>((const unsigned int*)ei_raw, flag);
    convert_kernel<<<(2 * NE + 255) / 256, 256>>>(ei_raw, flag, eidx);

    // prep
    pack3_kernel<<<(128 * 32 + 255) / 256, 256>>>(Wmu_rel, Wls_rel, Wmu_root, Wls_root,
                                                  bmu, bls, Wrel3, Wroot3, b3);
    deg_kernel<<<(NE + 255) / 256, 256>>>(edst, deg);
    dinv_kernel<<<(NN + 255) / 256, 256>>>(deg, dinv);

    const int MB = (NN + 127) / 128;  // 391

    // layer 1: aggregate x (64-wide), then fused dual GEMM -> h1 [NN,256]
    scatter_kernel<64><<<(NE * 16 + 255) / 256, 256>>>(esrc, edst, x, aggx);
    mm_kernel<64, true, false, true, false><<<dim3(MB, 4), 256>>>(
        aggx, W1_rel, x, W1_root, nullptr, dinv, b1, h1, NN, 64, 256);

    // layer 2: project h1 -> p2 [NN,128], aggregate, epilogue GEMM -> h2
    mm_kernel<64, false, false, false, false><<<dim3(MB, 2), 256>>>(
        h1, W2_rel, nullptr, nullptr, nullptr, nullptr, nullptr, p2, NN, 256, 128);
    scatter_kernel<128><<<(NE * 32 + 255) / 256, 256>>>(esrc, edst, p2, a2);
    mm_kernel<64, false, true, true, false><<<dim3(MB, 2), 256>>>(
        h1, W2_root, nullptr, nullptr, a2, dinv, b2, h2, NN, 256, 128);

    // heads: project h2 -> p3 [NN,32], aggregate, epilogue GEMM -> (mu|logstd)
    mm_kernel<32, false, false, false, false><<<dim3(MB, 1), 128>>>(
        h2, Wrel3, nullptr, nullptr, nullptr, nullptr, nullptr, p3, NN, 128, 32);
    scatter_kernel<32><<<(NE * 8 + 255) / 256, 256>>>(esrc, edst, p3, a3);
    mm_kernel<32, false, true, false, true><<<dim3(MB, 1), 128>>>(
        h2, Wroot3, nullptr, nullptr, a3, dinv, b3, out, NN, 128, 32);
}

// round 8
// speedup vs baseline: 1.4310x; 1.2233x over previous
#include <cuda_runtime.h>
#include <mma.h>

using namespace nvcuda;

#define NN 50000
#define NE 800000
#define IN_CH 64

// ---------------------------------------------------------------------------
// Scratch layout (single __device__ array). Only [0, ZERO_CNT) is memset per
// launch (flag + degree histogram). All offsets are multiples of 4 floats.
// ---------------------------------------------------------------------------
constexpr size_t OFF_FLAG   = 0;                               // [4] int
constexpr size_t OFF_DEGI   = OFF_FLAG + 4;                    // [NN] int
constexpr size_t ZERO_CNT   = OFF_DEGI + NN;                   // zeroed region end
constexpr size_t OFF_EXCL   = ZERO_CNT;                        // [NN] int
constexpr size_t OFF_BSUM   = OFF_EXCL + NN;                   // [256] int
constexpr size_t OFF_OFFS   = OFF_BSUM + 256;                  // [NN+16] int
constexpr size_t OFF_CURS   = OFF_OFFS + NN + 16;              // [NN] int
constexpr size_t OFF_EIDX   = OFF_CURS + NN;                   // [2*NE] int (src|dst)
constexpr size_t OFF_CSR    = OFF_EIDX + (size_t)2 * NE;       // [NE] int
constexpr size_t OFF_AGGX   = OFF_CSR  + NE;                   // [NN*64] float
constexpr size_t OFF_A2     = OFF_AGGX + (size_t)NN * 64;      // [NN*128]
constexpr size_t OFF_A3     = OFF_A2   + (size_t)NN * 128;     // [NN*32]
constexpr size_t OFF_H1     = OFF_A3   + (size_t)NN * 32;      // [NN*256]
constexpr size_t OFF_P2     = OFF_H1   + (size_t)NN * 256;     // [NN*128]
constexpr size_t OFF_H2     = OFF_P2   + (size_t)NN * 128;     // [NN*128]
constexpr size_t OFF_P3     = OFF_H2   + (size_t)NN * 128;     // [NN*32]
constexpr size_t OFF_WREL3  = OFF_P3   + (size_t)NN * 32;      // [128*32]
constexpr size_t OFF_WROOT3 = OFF_WREL3 + 128 * 32;            // [128*32]
constexpr size_t OFF_B3     = OFF_WROOT3 + 128 * 32;           // [32]
constexpr size_t TOTAL_F    = OFF_B3 + 32;

__device__ __align__(128) float g_scratch[TOTAL_F];

// ---------------------------------------------------------------------------
// Edge-index dtype detection + conversion (clamped to [0, NN) for safety).
// int64 little-endian with values < 50000 => every odd 32-bit word is 0.
// ---------------------------------------------------------------------------
__global__ void detect_kernel(const unsigned int* __restrict__ raw, int* __restrict__ flag) {
    int t = threadIdx.x;
    unsigned int v = 0;
    for (int i = t; i < 512; i += blockDim.x) v |= raw[2 * i + 1];
    if (__syncthreads_or(v != 0) && t == 0) *flag = 1;
}

__global__ void convert_kernel(const void* __restrict__ raw, const int* __restrict__ flag,
                               int* __restrict__ eidx) {
    int i = blockIdx.x * blockDim.x + threadIdx.x;
    if (i < 2 * NE) {
        int v = (*flag) ? ((const int*)raw)[i]
                        : (int)((const long long*)raw)[i];
        eidx[i] = min(max(v, 0), NN - 1);
    }
}

// ---------------------------------------------------------------------------
// CSR construction: histogram -> exclusive scan (3 kernels) -> bucket scatter
// ---------------------------------------------------------------------------
__global__ void hist_kernel(const int* __restrict__ dst, int* __restrict__ degi) {
    int e = blockIdx.x * blockDim.x + threadIdx.x;
    if (e < NE) atomicAdd(&degi[dst[e]], 1);
}

__global__ void scan1_kernel(const int* __restrict__ degi, int* __restrict__ excl,
                             int* __restrict__ bsum) {
    __shared__ int sm[256];
    int t = threadIdx.x;
    int i = blockIdx.x * 256 + t;
    int v = (i < NN) ? degi[i] : 0;
    sm[t] = v;
    __syncthreads();
    for (int off = 1; off < 256; off <<= 1) {
        int x = (t >= off) ? sm[t - off] : 0;
        __syncthreads();
        sm[t] += x;
        __syncthreads();
    }
    if (i < NN) excl[i] = sm[t] - v;
    if (t == 255) bsum[blockIdx.x] = sm[255];
}

__global__ void scan2_kernel(int* __restrict__ bsum, int nb) {
    __shared__ int sm[256];
    int t = threadIdx.x;
    int v = (t < nb) ? bsum[t] : 0;
    sm[t] = v;
    __syncthreads();
    for (int off = 1; off < 256; off <<= 1) {
        int x = (t >= off) ? sm[t - off] : 0;
        __syncthreads();
        sm[t] += x;
        __syncthreads();
    }
    if (t < nb) bsum[t] = sm[t] - v;   // exclusive
}

__global__ void scan3_kernel(const int* __restrict__ excl, const int* __restrict__ bsum,
                             int* __restrict__ offs, int* __restrict__ curs) {
    int i = blockIdx.x * blockDim.x + threadIdx.x;
    if (i < NN) {
        int o = excl[i] + bsum[i >> 8];
        offs[i] = o;
        curs[i] = o;
    }
    if (i == 0) offs[NN] = NE;
}

__global__ void csr_build_kernel(const int* __restrict__ esrc, const int* __restrict__ edst,
                                 int* __restrict__ curs, int* __restrict__ csr) {
    int e = blockIdx.x * blockDim.x + threadIdx.x;
    if (e < NE) {
        int p = atomicAdd(&curs[edst[e]], 1);
        csr[p] = esrc[e];
    }
}

// ---------------------------------------------------------------------------
// Segmented mean-aggregation: one warp per destination node.
// OUT[n,:] = (1/deg(n)) * sum_{s in N(n)} P[s,:]   (0 if deg==0)
// Coalesced stride-32 reads; register accumulate; plain stores (no atomics).
// ---------------------------------------------------------------------------
template <int D>
__global__ void agg_kernel(const int* __restrict__ offs, const int* __restrict__ csr,
                           const float* __restrict__ P, float* __restrict__ OUT) {
    constexpr int R = D / 32;
    int w = (blockIdx.x * blockDim.x + threadIdx.x) >> 5;
    int lane = threadIdx.x & 31;
    if (w >= NN) return;
    int s = offs[w], e = offs[w + 1];
    float acc[R] = {};
    int i = s;
    for (; i + 1 < e; i += 2) {
        const float* r0 = P + (size_t)csr[i] * D;
        const float* r1 = P + (size_t)csr[i + 1] * D;
#pragma unroll
        for (int r = 0; r < R; r++)
            acc[r] += __ldg(r0 + lane + 32 * r) + __ldg(r1 + lane + 32 * r);
    }
    if (i < e) {
        const float* r0 = P + (size_t)csr[i] * D;
#pragma unroll
        for (int r = 0; r < R; r++) acc[r] += __ldg(r0 + lane + 32 * r);
    }
    int deg = e - s;
    float sc = deg > 0 ? 1.0f / (float)deg : 0.0f;
#pragma unroll
    for (int r = 0; r < R; r++) OUT[(size_t)w * D + lane + 32 * r] = acc[r] * sc;
}

// ---------------------------------------------------------------------------
// Pack the 4 head weight matrices into concatenated [128,32] buffers
// ---------------------------------------------------------------------------
__global__ void pack3_kernel(const float* __restrict__ Wmu_rel, const float* __restrict__ Wls_rel,
                             const float* __restrict__ Wmu_root, const float* __restrict__ Wls_root,
                             const float* __restrict__ bmu, const float* __restrict__ bls,
                             float* __restrict__ Wrel3, float* __restrict__ Wroot3,
                             float* __restrict__ b3) {
    int i = blockIdx.x * blockDim.x + threadIdx.x;
    if (i < 128 * 32) {
        int k = i / 32, n = i % 32;
        Wrel3[i]  = (n < 16) ? Wmu_rel[k * 16 + n]  : Wls_rel[k * 16 + (n - 16)];
        Wroot3[i] = (n < 16) ? Wmu_root[k * 16 + n] : Wls_root[k * 16 + (n - 16)];
        if (i < 32) b3[i] = (i < 16) ? bmu[i] : bls[i - 16];
    }
}

// ---------------------------------------------------------------------------
// tf32 wmma GEMM: 128xBN block tile, BK=16, warps 4 x (BN/32), each warp
// 32x32 (2x2 m16n16k8 fragments), fp32 accumulate. tf32 convert at smem store.
// Aggregates arrive pre-scaled by 1/deg, so no dinv anywhere.
//
// DUAL    : c = A@W + A2@W2 (two phases, same K)
// HAS_ADD : epilogue += ADD[m,n]
// bias    : added if non-null
// RELU    : epilogue relu
// SPLIT   : N=32 -> cols [0,16) at OUT[m*16+n], cols [16,32) at OUT+NN*16
// ---------------------------------------------------------------------------
template <int BN, bool DUAL, bool HAS_ADD, bool RELU, bool SPLIT>
__global__ __launch_bounds__(32 * 4 * (BN / 32))
void mm_kernel(const float* __restrict__ A, const float* __restrict__ W,
               const float* __restrict__ A2, const float* __restrict__ W2,
               const float* __restrict__ ADD,
               const float* __restrict__ bias, float* __restrict__ OUT,
               int M, int K, int N) {
    constexpr int BM = 128, BK = 16;
    constexpr int WN = BN / 32;
    constexpr int NT = 128 * WN;
    constexpr int LDA = BK + 8;
    constexpr int LDB = BN + 8;
    constexpr int LDC = BN + 8;
    constexpr int SZ_AB = BM * LDA + BK * LDB;
    constexpr int SZ_C  = BM * LDC;
    constexpr int SMEM_FLOATS = SZ_AB > SZ_C ? SZ_AB : SZ_C;
    __shared__ __align__(16) float smem[SMEM_FLOATS];
    float* As = smem;
    float* Bs = smem + BM * LDA;
    float* Cs = smem;

    int t    = threadIdx.x;
    int warp = t >> 5;
    int wm   = warp & 3;
    int wn   = warp >> 2;
    int m0   = blockIdx.x * BM;
    int n0   = blockIdx.y * BN;

    wmma::fragment<wmma::accumulator, 16, 16, 8, float> c[2][2];
#pragma unroll
    for (int i = 0; i < 2; i++)
#pragma unroll
        for (int j = 0; j < 2; j++) wmma::fill_fragment(c[i][j], 0.0f);

    const int nPhase = DUAL ? 2 : 1;
    for (int ph = 0; ph < nPhase; ph++) {
        const float* Ap = (DUAL && ph == 1) ? A2 : A;
        const float* Wp = (DUAL && ph == 1) ? W2 : W;
        for (int k0 = 0; k0 < K; k0 += BK) {
            for (int i = t; i < BM * BK / 4; i += NT) {
                int row = i / (BK / 4);
                int c4  = i % (BK / 4);
                float4 v = make_float4(0.f, 0.f, 0.f, 0.f);
                int m = m0 + row;
                if (m < M) v = *(const float4*)(Ap + (size_t)m * K + k0 + c4 * 4);
                float* d = As + row * LDA + c4 * 4;
                d[0] = wmma::__float_to_tf32(v.x);
                d[1] = wmma::__float_to_tf32(v.y);
                d[2] = wmma::__float_to_tf32(v.z);
                d[3] = wmma::__float_to_tf32(v.w);
            }
            for (int i = t; i < BK * BN / 4; i += NT) {
                int row = i / (BN / 4);
                int c4  = i % (BN / 4);
                float4 v = *(const float4*)(Wp + (size_t)(k0 + row) * N + n0 + c4 * 4);
                float* d = Bs + row * LDB + c4 * 4;
                d[0] = wmma::__float_to_tf32(v.x);
                d[1] = wmma::__float_to_tf32(v.y);
                d[2] = wmma::__float_to_tf32(v.z);
                d[3] = wmma::__float_to_tf32(v.w);
            }
            __syncthreads();
#pragma unroll
            for (int kk = 0; kk < BK; kk += 8) {
                wmma::fragment<wmma::matrix_a, 16, 16, 8, wmma::precision::tf32, wmma::row_major> a[2];
                wmma::fragment<wmma::matrix_b, 16, 16, 8, wmma::precision::tf32, wmma::row_major> b[2];
#pragma unroll
                for (int i = 0; i < 2; i++)
                    wmma::load_matrix_sync(a[i], As + (wm * 32 + i * 16) * LDA + kk, LDA);
#pragma unroll
                for (int j = 0; j < 2; j++)
                    wmma::load_matrix_sync(b[j], Bs + kk * LDB + wn * 32 + j * 16, LDB);
#pragma unroll
                for (int i = 0; i < 2; i++)
#pragma unroll
                    for (int j = 0; j < 2; j++)
                        wmma::mma_sync(c[i][j], a[i], b[j], c[i][j]);
            }
            __syncthreads();
        }
    }

#pragma unroll
    for (int i = 0; i < 2; i++)
#pragma unroll
        for (int j = 0; j < 2; j++)
            wmma::store_matrix_sync(Cs + (wm * 32 + i * 16) * LDC + wn * 32 + j * 16,
                                    c[i][j], LDC, wmma::mem_row_major);
    __syncthreads();

    for (int i = t; i < BM * BN / 4; i += NT) {
        int row = i / (BN / 4);
        int c4  = i % (BN / 4);
        int m = m0 + row;
        if (m >= M) continue;
        float4 v = *(float4*)(Cs + row * LDC + c4 * 4);
        int n = n0 + c4 * 4;
        if (bias) {
            v.x += bias[n + 0]; v.y += bias[n + 1];
            v.z += bias[n + 2]; v.w += bias[n + 3];
        }
        if (HAS_ADD) {
            const float4 av = *(const float4*)(ADD + (size_t)m * N + n);
            v.x += av.x; v.y += av.y; v.z += av.z; v.w += av.w;
        }
        if (RELU) {
            v.x = fmaxf(v.x, 0.f); v.y = fmaxf(v.y, 0.f);
            v.z = fmaxf(v.z, 0.f); v.w = fmaxf(v.w, 0.f);
        }
        if (SPLIT) {
            float* dptr = (n < 16) ? (OUT + (size_t)m * 16 + n)
                                   : (OUT + (size_t)NN * 16 + (size_t)m * 16 + (n - 16));
            *(float4*)dptr = v;
        } else {
            *(float4*)(OUT + (size_t)m * N + n) = v;
        }
    }
}

// ---------------------------------------------------------------------------
// Launch
// ---------------------------------------------------------------------------
extern "C" void kernel_launch(void* const* d_in, const int* in_sizes, int n_in,
                              void* d_out, int out_size) {
    const float *x, *W1_rel, *b1, *W1_root, *W2_rel, *b2, *W2_root;
    const float *Wmu_rel, *bmu, *Wmu_root, *Wls_rel, *bls, *Wls_root;
    const void* ei_raw;

    if (in_sizes[0] == NN * IN_CH) {
        // dict order
        x        = (const float*)d_in[0];
        W1_rel   = (const float*)d_in[1];
        b1       = (const float*)d_in[2];
        W1_root  = (const float*)d_in[3];
        W2_rel   = (const float*)d_in[4];
        b2       = (const float*)d_in[5];
        W2_root  = (const float*)d_in[6];
        Wmu_rel  = (const float*)d_in[7];
        bmu      = (const float*)d_in[8];
        Wmu_root = (const float*)d_in[9];
        Wls_rel  = (const float*)d_in[10];
        bls      = (const float*)d_in[11];
        Wls_root = (const float*)d_in[12];
        ei_raw   = d_in[13];
    } else {
        // alphabetical order
        W1_rel   = (const float*)d_in[0];
        W1_root  = (const float*)d_in[1];
        W2_rel   = (const float*)d_in[2];
        W2_root  = (const float*)d_in[3];
        Wls_rel  = (const float*)d_in[4];
        Wls_root = (const float*)d_in[5];
        Wmu_rel  = (const float*)d_in[6];
        Wmu_root = (const float*)d_in[7];
        b1       = (const float*)d_in[8];
        b2       = (const float*)d_in[9];
        bls      = (const float*)d_in[10];
        bmu      = (const float*)d_in[11];
        ei_raw   = d_in[12];
        x        = (const float*)d_in[13];
    }
    float* out = (float*)d_out;

    float* base = nullptr;
    cudaGetSymbolAddress((void**)&base, g_scratch);
    int*   flag   = (int*)(base + OFF_FLAG);
    int*   degi   = (int*)(base + OFF_DEGI);
    int*   excl   = (int*)(base + OFF_EXCL);
    int*   bsum   = (int*)(base + OFF_BSUM);
    int*   offs   = (int*)(base + OFF_OFFS);
    int*   curs   = (int*)(base + OFF_CURS);
    int*   eidx   = (int*)(base + OFF_EIDX);
    int*   csr    = (int*)(base + OFF_CSR);
    int*   esrc   = eidx;
    int*   edst   = eidx + NE;
    float* aggx   = base + OFF_AGGX;
    float* a2     = base + OFF_A2;
    float* a3     = base + OFF_A3;
    float* h1     = base + OFF_H1;
    float* p2     = base + OFF_P2;
    float* h2     = base + OFF_H2;
    float* p3     = base + OFF_P3;
    float* Wrel3  = base + OFF_WREL3;
    float* Wroot3 = base + OFF_WROOT3;
    float* b3     = base + OFF_B3;

    // zero flag + degree histogram only (~200KB)
    cudaMemsetAsync(base, 0, ZERO_CNT * sizeof(float), 0);

    // edge-index dtype detection + conversion to clamped int32 src/dst arrays
    detect_kernel<<<1, 256>>>((const unsigned int*)ei_raw, flag);
    convert_kernel<<<(2 * NE + 255) / 256, 256>>>(ei_raw, flag, eidx);

    pack3_kernel<<<(128 * 32 + 255) / 256, 256>>>(Wmu_rel, Wls_rel, Wmu_root, Wls_root,
                                                  bmu, bls, Wrel3, Wroot3, b3);

    // CSR build: histogram -> scan -> bucket scatter
    const int NB = (NN + 255) / 256;  // 196
    hist_kernel<<<(NE + 255) / 256, 256>>>(edst, degi);
    scan1_kernel<<<NB, 256>>>(degi, excl, bsum);
    scan2_kernel<<<1, 256>>>(bsum, NB);
    scan3_kernel<<<NB, 256>>>(excl, bsum, offs, curs);
    csr_build_kernel<<<(NE + 255) / 256, 256>>>(esrc, edst, curs, csr);

    const int MB = (NN + 127) / 128;     // 391
    const int AGG_BLOCKS = (NN + 7) / 8; // 8 warps/block

    // layer 1: mean-aggregate x (64-wide), fused dual GEMM -> h1 [NN,256]
    agg_kernel<64><<<AGG_BLOCKS, 256>>>(offs, csr, x, aggx);
    mm_kernel<64, true, false, true, false><<<dim3(MB, 4), 256>>>(
        aggx, W1_rel, x, W1_root, nullptr, b1, h1, NN, 64, 256);

    // layer 2: project h1 -> p2 [NN,128], aggregate, epilogue GEMM -> h2
    mm_kernel<64, false, false, false, false><<<dim3(MB, 2), 256>>>(
        h1, W2_rel, nullptr, nullptr, nullptr, nullptr, p2, NN, 256, 128);
    agg_kernel<128><<<AGG_BLOCKS, 256>>>(offs, csr, p2, a2);
    mm_kernel<64, false, true, true, false><<<dim3(MB, 2), 256>>>(
        h1, W2_root, nullptr, nullptr, a2, b2, h2, NN, 256, 128);

    // heads: project h2 -> p3 [NN,32], aggregate, epilogue GEMM -> (mu|logstd)
    mm_kernel<32, false, false, false, false><<<dim3(MB, 1), 128>>>(
        h2, Wrel3, nullptr, nullptr, nullptr, nullptr, p3, NN, 128, 32);
    agg_kernel<32><<<AGG_BLOCKS, 256>>>(offs, csr, p3, a3);
    mm_kernel<32, false, true, false, true><<<dim3(MB, 1), 128>>>(
        h2, Wroot3, nullptr, nullptr, a3, b3, out, NN, 128, 32);
}

// round 10
// speedup vs baseline: 1.4822x; 1.0358x over previous
#include <cuda_runtime.h>
#include <mma.h>

using namespace nvcuda;

#define NN 50000
#define NE 800000
#define IN_CH 64

// ---------------------------------------------------------------------------
// Scratch layout (single __device__ array). Only [0, ZERO_CNT) is memset per
// launch (flag + degree histogram). All offsets are multiples of 4 floats.
// ---------------------------------------------------------------------------
constexpr size_t OFF_FLAG   = 0;                               // [4] int
constexpr size_t OFF_DEGI   = OFF_FLAG + 4;                    // [NN] int
constexpr size_t ZERO_CNT   = OFF_DEGI + NN;                   // zeroed region end
constexpr size_t OFF_EXCL   = ZERO_CNT;                        // [NN] int
constexpr size_t OFF_BSUM   = OFF_EXCL + NN;                   // [256] int
constexpr size_t OFF_OFFS   = OFF_BSUM + 256;                  // [NN+16] int
constexpr size_t OFF_CURS   = OFF_OFFS + NN + 16;              // [NN] int
constexpr size_t OFF_EIDX   = OFF_CURS + NN;                   // [2*NE] int (src|dst)
constexpr size_t OFF_CSR    = OFF_EIDX + (size_t)2 * NE;       // [NE] int
constexpr size_t OFF_AGGX   = OFF_CSR  + NE;                   // [NN*64] float
constexpr size_t OFF_H1     = OFF_AGGX + (size_t)NN * 64;      // [NN*256]
constexpr size_t OFF_P2     = OFF_H1   + (size_t)NN * 256;     // [NN*128]
constexpr size_t OFF_H2     = OFF_P2   + (size_t)NN * 128;     // [NN*128]
constexpr size_t OFF_P3     = OFF_H2   + (size_t)NN * 128;     // [NN*32]
constexpr size_t OFF_T1     = OFF_P3   + (size_t)NN * 32;      // [NN*256]
constexpr size_t OFF_T2     = OFF_T1   + (size_t)NN * 256;     // [NN*128]
constexpr size_t OFF_T3     = OFF_T2   + (size_t)NN * 128;     // [NN*32]
constexpr size_t OFF_WREL3  = OFF_T3   + (size_t)NN * 32;      // [128*32]
constexpr size_t OFF_WROOT3 = OFF_WREL3 + 128 * 32;            // [128*32]
constexpr size_t OFF_B3     = OFF_WROOT3 + 128 * 32;           // [32]
constexpr size_t TOTAL_F    = OFF_B3 + 32;

__device__ __align__(128) float g_scratch[TOTAL_F];

// ---------------------------------------------------------------------------
// Edge-index dtype detection + conversion (clamped to [0, NN) for safety).
// ---------------------------------------------------------------------------
__global__ void detect_kernel(const unsigned int* __restrict__ raw, int* __restrict__ flag) {
    int t = threadIdx.x;
    unsigned int v = 0;
    for (int i = t; i < 512; i += blockDim.x) v |= raw[2 * i + 1];
    if (__syncthreads_or(v != 0) && t == 0) *flag = 1;
}

__global__ void convert_kernel(const void* __restrict__ raw, const int* __restrict__ flag,
                               int* __restrict__ eidx) {
    int i = blockIdx.x * blockDim.x + threadIdx.x;
    if (i < 2 * NE) {
        int v = (*flag) ? ((const int*)raw)[i]
                        : (int)((const long long*)raw)[i];
        eidx[i] = min(max(v, 0), NN - 1);
    }
}

// ---------------------------------------------------------------------------
// CSR construction: histogram -> exclusive scan (3 kernels) -> bucket scatter
// ---------------------------------------------------------------------------
__global__ void hist_kernel(const int* __restrict__ dst, int* __restrict__ degi) {
    int e = blockIdx.x * blockDim.x + threadIdx.x;
    if (e < NE) atomicAdd(&degi[dst[e]], 1);
}

__global__ void scan1_kernel(const int* __restrict__ degi, int* __restrict__ excl,
                             int* __restrict__ bsum) {
    __shared__ int sm[256];
    int t = threadIdx.x;
    int i = blockIdx.x * 256 + t;
    int v = (i < NN) ? degi[i] : 0;
    sm[t] = v;
    __syncthreads();
    for (int off = 1; off < 256; off <<= 1) {
        int x = (t >= off) ? sm[t - off] : 0;
        __syncthreads();
        sm[t] += x;
        __syncthreads();
    }
    if (i < NN) excl[i] = sm[t] - v;
    if (t == 255) bsum[blockIdx.x] = sm[255];
}

__global__ void scan2_kernel(int* __restrict__ bsum, int nb) {
    __shared__ int sm[256];
    int t = threadIdx.x;
    int v = (t < nb) ? bsum[t] : 0;
    sm[t] = v;
    __syncthreads();
    for (int off = 1; off < 256; off <<= 1) {
        int x = (t >= off) ? sm[t - off] : 0;
        __syncthreads();
        sm[t] += x;
        __syncthreads();
    }
    if (t < nb) bsum[t] = sm[t] - v;   // exclusive
}

__global__ void scan3_kernel(const int* __restrict__ excl, const int* __restrict__ bsum,
                             int* __restrict__ offs, int* __restrict__ curs) {
    int i = blockIdx.x * blockDim.x + threadIdx.x;
    if (i < NN) {
        int o = excl[i] + bsum[i >> 8];
        offs[i] = o;
        curs[i] = o;
    }
    if (i == 0) offs[NN] = NE;
}

__global__ void csr_build_kernel(const int* __restrict__ esrc, const int* __restrict__ edst,
                                 int* __restrict__ curs, int* __restrict__ csr) {
    int e = blockIdx.x * blockDim.x + threadIdx.x;
    if (e < NE) {
        int p = atomicAdd(&curs[edst[e]], 1);
        csr[p] = esrc[e];
    }
}

// ---------------------------------------------------------------------------
// Segmented mean-aggregation: one warp per destination node, 4-edge unroll.
// OUT[n,:] = f( (1/deg) * sum_{s in N(n)} P[s,:]  [+ T[n,:]] )
// HAS_ADD: add root-path result T; RELU; SPLIT: N=32 mu/logstd split store.
// ---------------------------------------------------------------------------
template <int D, bool HAS_ADD, bool RELU, bool SPLIT>
__global__ void agg_kernel(const int* __restrict__ offs, const int* __restrict__ csr,
                           const float* __restrict__ P, const float* __restrict__ T,
                           float* __restrict__ OUT) {
    constexpr int R = D / 32;
    int w = (blockIdx.x * blockDim.x + threadIdx.x) >> 5;
    int lane = threadIdx.x & 31;
    if (w >= NN) return;
    int s = offs[w], e = offs[w + 1];
    float acc[R] = {};
    int i = s;
    for (; i + 3 < e; i += 4) {
        const float* r0 = P + (size_t)csr[i] * D;
        const float* r1 = P + (size_t)csr[i + 1] * D;
        const float* r2 = P + (size_t)csr[i + 2] * D;
        const float* r3 = P + (size_t)csr[i + 3] * D;
#pragma unroll
        for (int r = 0; r < R; r++)
            acc[r] += (__ldg(r0 + lane + 32 * r) + __ldg(r1 + lane + 32 * r))
                    + (__ldg(r2 + lane + 32 * r) + __ldg(r3 + lane + 32 * r));
    }
    for (; i < e; i++) {
        const float* r0 = P + (size_t)csr[i] * D;
#pragma unroll
        for (int r = 0; r < R; r++) acc[r] += __ldg(r0 + lane + 32 * r);
    }
    int deg = e - s;
    float sc = deg > 0 ? 1.0f / (float)deg : 0.0f;
#pragma unroll
    for (int r = 0; r < R; r++) {
        int col = lane + 32 * r;
        float v = acc[r] * sc;
        if (HAS_ADD) v += T[(size_t)w * D + col];
        if (RELU) v = fmaxf(v, 0.f);
        if (SPLIT) {
            float* p = (col < 16) ? (OUT + (size_t)w * 16 + col)
                                  : (OUT + (size_t)NN * 16 + (size_t)w * 16 + (col - 16));
            *p = v;
        } else {
            OUT[(size_t)w * D + col] = v;
        }
    }
}

// ---------------------------------------------------------------------------
// Pack the 4 head weight matrices into concatenated [128,32] buffers
// ---------------------------------------------------------------------------
__global__ void pack3_kernel(const float* __restrict__ Wmu_rel, const float* __restrict__ Wls_rel,
                             const float* __restrict__ Wmu_root, const float* __restrict__ Wls_root,
                             const float* __restrict__ bmu, const float* __restrict__ bls,
                             float* __restrict__ Wrel3, float* __restrict__ Wroot3,
                             float* __restrict__ b3) {
    int i = blockIdx.x * blockDim.x + threadIdx.x;
    if (i < 128 * 32) {
        int k = i / 32, n = i % 32;
        Wrel3[i]  = (n < 16) ? Wmu_rel[k * 16 + n]  : Wls_rel[k * 16 + (n - 16)];
        Wroot3[i] = (n < 16) ? Wmu_root[k * 16 + n] : Wls_root[k * 16 + (n - 16)];
        if (i < 32) b3[i] = (i < 16) ? bmu[i] : bls[i - 16];
    }
}

// ---------------------------------------------------------------------------
// tf32 wmma GEMM: 128xBN block tile, BK=16, warps 4 x (BN/32), each warp
// 32x32 (2x2 m16n16k8 fragments), fp32 accumulate. tf32 convert at smem store.
// HAS_ADD: epilogue += ADD[m,n]; bias: added if non-null; RELU.
// ---------------------------------------------------------------------------
template <int BN, bool HAS_ADD, bool RELU>
__global__ __launch_bounds__(32 * 4 * (BN / 32))
void mm_kernel(const float* __restrict__ A, const float* __restrict__ W,
               const float* __restrict__ ADD,
               const float* __restrict__ bias, float* __restrict__ OUT,
               int M, int K, int N) {
    constexpr int BM = 128, BK = 16;
    constexpr int WN = BN / 32;
    constexpr int NT = 128 * WN;
    constexpr int LDA = BK + 8;
    constexpr int LDB = BN + 8;
    constexpr int LDC = BN + 8;
    constexpr int SZ_AB = BM * LDA + BK * LDB;
    constexpr int SZ_C  = BM * LDC;
    constexpr int SMEM_FLOATS = SZ_AB > SZ_C ? SZ_AB : SZ_C;
    __shared__ __align__(16) float smem[SMEM_FLOATS];
    float* As = smem;
    float* Bs = smem + BM * LDA;
    float* Cs = smem;

    int t    = threadIdx.x;
    int warp = t >> 5;
    int wm   = warp & 3;
    int wn   = warp >> 2;
    int m0   = blockIdx.x * BM;
    int n0   = blockIdx.y * BN;

    wmma::fragment<wmma::accumulator, 16, 16, 8, float> c[2][2];
#pragma unroll
    for (int i = 0; i < 2; i++)
#pragma unroll
        for (int j = 0; j < 2; j++) wmma::fill_fragment(c[i][j], 0.0f);

    for (int k0 = 0; k0 < K; k0 += BK) {
        for (int i = t; i < BM * BK / 4; i += NT) {
            int row = i / (BK / 4);
            int c4  = i % (BK / 4);
            float4 v = make_float4(0.f, 0.f, 0.f, 0.f);
            int m = m0 + row;
            if (m < M) v = *(const float4*)(A + (size_t)m * K + k0 + c4 * 4);
            float* d = As + row * LDA + c4 * 4;
            d[0] = wmma::__float_to_tf32(v.x);
            d[1] = wmma::__float_to_tf32(v.y);
            d[2] = wmma::__float_to_tf32(v.z);
            d[3] = wmma::__float_to_tf32(v.w);
        }
        for (int i = t; i < BK * BN / 4; i += NT) {
            int row = i / (BN / 4);
            int c4  = i % (BN / 4);
            float4 v = *(const float4*)(W + (size_t)(k0 + row) * N + n0 + c4 * 4);
            float* d = Bs + row * LDB + c4 * 4;
            d[0] = wmma::__float_to_tf32(v.x);
            d[1] = wmma::__float_to_tf32(v.y);
            d[2] = wmma::__float_to_tf32(v.z);
            d[3] = wmma::__float_to_tf32(v.w);
        }
        __syncthreads();
#pragma unroll
        for (int kk = 0; kk < BK; kk += 8) {
            wmma::fragment<wmma::matrix_a, 16, 16, 8, wmma::precision::tf32, wmma::row_major> a[2];
            wmma::fragment<wmma::matrix_b, 16, 16, 8, wmma::precision::tf32, wmma::row_major> b[2];
#pragma unroll
            for (int i = 0; i < 2; i++)
                wmma::load_matrix_sync(a[i], As + (wm * 32 + i * 16) * LDA + kk, LDA);
#pragma unroll
            for (int j = 0; j < 2; j++)
                wmma::load_matrix_sync(b[j], Bs + kk * LDB + wn * 32 + j * 16, LDB);
#pragma unroll
            for (int i = 0; i < 2; i++)
#pragma unroll
                for (int j = 0; j < 2; j++)
                    wmma::mma_sync(c[i][j], a[i], b[j], c[i][j]);
        }
        __syncthreads();
    }

#pragma unroll
    for (int i = 0; i < 2; i++)
#pragma unroll
        for (int j = 0; j < 2; j++)
            wmma::store_matrix_sync(Cs + (wm * 32 + i * 16) * LDC + wn * 32 + j * 16,
                                    c[i][j], LDC, wmma::mem_row_major);
    __syncthreads();

    for (int i = t; i < BM * BN / 4; i += NT) {
        int row = i / (BN / 4);
        int c4  = i % (BN / 4);
        int m = m0 + row;
        if (m >= M) continue;
        float4 v = *(float4*)(Cs + row * LDC + c4 * 4);
        int n = n0 + c4 * 4;
        if (bias) {
            v.x += bias[n + 0]; v.y += bias[n + 1];
            v.z += bias[n + 2]; v.w += bias[n + 3];
        }
        if (HAS_ADD) {
            const float4 av = *(const float4*)(ADD + (size_t)m * N + n);
            v.x += av.x; v.y += av.y; v.z += av.z; v.w += av.w;
        }
        if (RELU) {
            v.x = fmaxf(v.x, 0.f); v.y = fmaxf(v.y, 0.f);
            v.z = fmaxf(v.z, 0.f); v.w = fmaxf(v.w, 0.f);
        }
        *(float4*)(OUT + (size_t)m * N + n) = v;
    }
}

// ---------------------------------------------------------------------------
// Launch: two-stream fork/join. Stream 0 (capture stream) runs the edge path
// (CSR build, aggregations, rel GEMMs); s2 runs the root-path GEMMs.
// ---------------------------------------------------------------------------
extern "C" void kernel_launch(void* const* d_in, const int* in_sizes, int n_in,
                              void* d_out, int out_size) {
    const float *x, *W1_rel, *b1, *W1_root, *W2_rel, *b2, *W2_root;
    const float *Wmu_rel, *bmu, *Wmu_root, *Wls_rel, *bls, *Wls_root;
    const void* ei_raw;

    if (in_sizes[0] == NN * IN_CH) {
        // dict order
        x        = (const float*)d_in[0];
        W1_rel   = (const float*)d_in[1];
        b1       = (const float*)d_in[2];
        W1_root  = (const float*)d_in[3];
        W2_rel   = (const float*)d_in[4];
        b2       = (const float*)d_in[5];
        W2_root  = (const float*)d_in[6];
        Wmu_rel  = (const float*)d_in[7];
        bmu      = (const float*)d_in[8];
        Wmu_root = (const float*)d_in[9];
        Wls_rel  = (const float*)d_in[10];
        bls      = (const float*)d_in[11];
        Wls_root = (const float*)d_in[12];
        ei_raw   = d_in[13];
    } else {
        // alphabetical order
        W1_rel   = (const float*)d_in[0];
        W1_root  = (const float*)d_in[1];
        W2_rel   = (const float*)d_in[2];
        W2_root  = (const float*)d_in[3];
        Wls_rel  = (const float*)d_in[4];
        Wls_root = (const float*)d_in[5];
        Wmu_rel  = (const float*)d_in[6];
        Wmu_root = (const float*)d_in[7];
        b1       = (const float*)d_in[8];
        b2       = (const float*)d_in[9];
        bls      = (const float*)d_in[10];
        bmu      = (const float*)d_in[11];
        ei_raw   = d_in[12];
        x        = (const float*)d_in[13];
    }
    float* out = (float*)d_out;

    float* base = nullptr;
    cudaGetSymbolAddress((void**)&base, g_scratch);
    int*   flag   = (int*)(base + OFF_FLAG);
    int*   degi   = (int*)(base + OFF_DEGI);
    int*   excl   = (int*)(base + OFF_EXCL);
    int*   bsum   = (int*)(base + OFF_BSUM);
    int*   offs   = (int*)(base + OFF_OFFS);
    int*   curs   = (int*)(base + OFF_CURS);
    int*   eidx   = (int*)(base + OFF_EIDX);
    int*   csr    = (int*)(base + OFF_CSR);
    int*   esrc   = eidx;
    int*   edst   = eidx + NE;
    float* aggx   = base + OFF_AGGX;
    float* h1     = base + OFF_H1;
    float* p2     = base + OFF_P2;
    float* h2     = base + OFF_H2;
    float* p3     = base + OFF_P3;
    float* t1     = base + OFF_T1;
    float* t2     = base + OFF_T2;
    float* t3     = base + OFF_T3;
    float* Wrel3  = base + OFF_WREL3;
    float* Wroot3 = base + OFF_WROOT3;
    float* b3     = base + OFF_B3;

    // One-time stream/event creation (outside capture on the correctness run;
    // reused identically on every call -> deterministic work).
    static cudaStream_t s2 = nullptr;
    static cudaEvent_t evRoot, evT1, evH1, evT2, evH2, evT3;
    if (!s2) {
        cudaStreamCreateWithFlags(&s2, cudaStreamNonBlocking);
        cudaEventCreateWithFlags(&evRoot, cudaEventDisableTiming);
        cudaEventCreateWithFlags(&evT1, cudaEventDisableTiming);
        cudaEventCreateWithFlags(&evH1, cudaEventDisableTiming);
        cudaEventCreateWithFlags(&evT2, cudaEventDisableTiming);
        cudaEventCreateWithFlags(&evH2, cudaEventDisableTiming);
        cudaEventCreateWithFlags(&evT3, cudaEventDisableTiming);
    }
    cudaStream_t s0 = 0;

    const int MB = (NN + 127) / 128;     // 391
    const int AGG_BLOCKS = (NN + 7) / 8; // 8 warps/block
    const int NB = (NN + 255) / 256;     // 196

    // fork s2 off the capture stream
    cudaEventRecord(evRoot, s0);
    cudaStreamWaitEvent(s2, evRoot, 0);

    // ---- s2: root path prologue (independent of edges) ----
    pack3_kernel<<<(128 * 32 + 255) / 256, 256, 0, s2>>>(
        Wmu_rel, Wls_rel, Wmu_root, Wls_root, bmu, bls, Wrel3, Wroot3, b3);
    mm_kernel<64, false, false><<<dim3(MB, 4), 256, 0, s2>>>(
        x, W1_root, nullptr, b1, t1, NN, 64, 256);                 // t1 = x@W1_root + b1
    cudaEventRecord(evT1, s2);

    // ---- s0: edge path (CSR build + aggx) ----
    cudaMemsetAsync(base, 0, ZERO_CNT * sizeof(float), s0);
    detect_kernel<<<1, 256, 0, s0>>>((const unsigned int*)ei_raw, flag);
    convert_kernel<<<(2 * NE + 255) / 256, 256, 0, s0>>>(ei_raw, flag, eidx);
    hist_kernel<<<(NE + 255) / 256, 256, 0, s0>>>(edst, degi);
    scan1_kernel<<<NB, 256, 0, s0>>>(degi, excl, bsum);
    scan2_kernel<<<1, 256, 0, s0>>>(bsum, NB);
    scan3_kernel<<<NB, 256, 0, s0>>>(excl, bsum, offs, curs);
    csr_build_kernel<<<(NE + 255) / 256, 256, 0, s0>>>(esrc, edst, curs, csr);
    agg_kernel<64, false, false, false><<<AGG_BLOCKS, 256, 0, s0>>>(
        offs, csr, x, nullptr, aggx);

    // ---- layer 1 combine: h1 = relu(aggx@W1_rel + t1) ----
    cudaStreamWaitEvent(s0, evT1, 0);
    mm_kernel<64, true, true><<<dim3(MB, 4), 256, 0, s0>>>(
        aggx, W1_rel, t1, nullptr, h1, NN, 64, 256);
    cudaEventRecord(evH1, s0);

    // ---- s2: t2 = h1@W2_root + b2 (overlaps p2 projection on s0) ----
    cudaStreamWaitEvent(s2, evH1, 0);
    mm_kernel<64, false, false><<<dim3(MB, 2), 256, 0, s2>>>(
        h1, W2_root, nullptr, b2, t2, NN, 256, 128);
    cudaEventRecord(evT2, s2);

    // ---- s0: p2 = h1@W2_rel; h2 = relu(agg(p2) + t2) ----
    mm_kernel<64, false, false><<<dim3(MB, 2), 256, 0, s0>>>(
        h1, W2_rel, nullptr, nullptr, p2, NN, 256, 128);
    cudaStreamWaitEvent(s0, evT2, 0);
    agg_kernel<128, true, true, false><<<AGG_BLOCKS, 256, 0, s0>>>(
        offs, csr, p2, t2, h2);
    cudaEventRecord(evH2, s0);

    // ---- s2: t3 = h2@Wroot3 + b3 (overlaps p3 projection on s0) ----
    cudaStreamWaitEvent(s2, evH2, 0);
    mm_kernel<32, false, false><<<dim3(MB, 1), 128, 0, s2>>>(
        h2, Wroot3, nullptr, b3, t3, NN, 128, 32);
    cudaEventRecord(evT3, s2);

    // ---- s0: p3 = h2@Wrel3; out = agg(p3) + t3 (split mu/logstd) ----
    mm_kernel<32, false, false><<<dim3(MB, 1), 128, 0, s0>>>(
        h2, Wrel3, nullptr, nullptr, p3, NN, 128, 32);
    cudaStreamWaitEvent(s0, evT3, 0);
    agg_kernel<32, true, false, true><<<AGG_BLOCKS, 256, 0, s0>>>(
        offs, csr, p3, t3, out);
}